// round 2
// baseline (speedup 1.0000x reference)
#include <cuda_runtime.h>
#include <cuda_bf16.h>
#include <cstddef>

#define T_STEPS 512
#define B_SIZE  512
#define NIN     64
#define H1      100
#define H2      50
#define H3      25
#define M_ROWS  (T_STEPS * B_SIZE)   // 262144

// Scratch: static device globals. Kernels reference them directly.
__device__ float g_xg[(size_t)M_ROWS * 4 * H1];   // 419 MB, reused per layer
__device__ float g_h [(size_t)M_ROWS * H1];       // 105 MB, reused per layer

__device__ __forceinline__ float sigf(float x) {
    return 1.0f / (1.0f + __expf(-x));
}
__device__ __forceinline__ float tanhf_(float x) {
    return 1.0f - 2.0f / (__expf(2.0f * x) + 1.0f);
}

// ---------------------------------------------------------------------------
// xg GEMM: g_xg[M, N] = inp[M, K] @ w[N, K]^T + bia[N] + bib[N]
// inp == nullptr means "read from g_h" (layers 2 and 3).
// M = 262144 fixed, TM = 128 rows per CTA, 256 threads.
// ---------------------------------------------------------------------------
template <int K>
__global__ void xg_gemm(const float* __restrict__ inp_,
                        const float* __restrict__ w,
                        const float* __restrict__ bia,
                        const float* __restrict__ bib,
                        int N)
{
    const float* inp = (inp_ != nullptr) ? inp_ : (const float*)g_h;

    constexpr int KP = (K + 3) & ~3;
    constexpr int TM = 128;
    extern __shared__ float sm[];
    float* w_s = sm;                   // N * KP
    float* a_s = sm + (size_t)N * KP;  // TM * KP

    const int tid = threadIdx.x;
    const size_t m0 = (size_t)blockIdx.x * TM;

    for (int idx = tid; idx < N * KP; idx += 256) {
        int n = idx / KP, k = idx - n * KP;
        w_s[idx] = (k < K) ? w[n * K + k] : 0.0f;
    }
    for (int idx = tid; idx < TM * KP; idx += 256) {
        int r = idx / KP, k = idx - r * KP;
        a_s[idx] = (k < K) ? inp[(m0 + r) * K + k] : 0.0f;
    }
    __syncthreads();

    const int tr = tid >> 4;
    const int tc = tid & 15;
    const int r0 = tr * 8;

    for (int nc = 0; nc < N; nc += 64) {
        float acc[8][4];
        #pragma unroll
        for (int u = 0; u < 8; ++u)
            #pragma unroll
            for (int v = 0; v < 4; ++v) acc[u][v] = 0.0f;

        int nv[4];
        #pragma unroll
        for (int v = 0; v < 4; ++v) {
            int n = nc + tc + v * 16;
            nv[v] = (n < N) ? n : 0;
        }

        for (int k = 0; k < KP; k += 4) {
            float4 wv[4];
            #pragma unroll
            for (int v = 0; v < 4; ++v)
                wv[v] = *(const float4*)&w_s[nv[v] * KP + k];
            #pragma unroll
            for (int u = 0; u < 8; ++u) {
                float4 av = *(const float4*)&a_s[(r0 + u) * KP + k];
                #pragma unroll
                for (int v = 0; v < 4; ++v) {
                    acc[u][v] = fmaf(av.x, wv[v].x, acc[u][v]);
                    acc[u][v] = fmaf(av.y, wv[v].y, acc[u][v]);
                    acc[u][v] = fmaf(av.z, wv[v].z, acc[u][v]);
                    acc[u][v] = fmaf(av.w, wv[v].w, acc[u][v]);
                }
            }
        }

        #pragma unroll
        for (int v = 0; v < 4; ++v) {
            int n = nc + tc + v * 16;
            if (n < N) {
                float bb = bia[n] + bib[n];
                #pragma unroll
                for (int u = 0; u < 8; ++u)
                    g_xg[(m0 + r0 + u) * N + n] = acc[u][v] + bb;
            }
        }
    }
}

// ---------------------------------------------------------------------------
// LSTM scan: per CTA, BT batch elements for all T steps. No inter-CTA sync.
// blockDim = 4*H threads, thread j owns gate row j.
// reads g_xg [T, B, 4H] (biases already added), whh [4H, H]; writes g_h [T, B, H]
// ---------------------------------------------------------------------------
template <int H, int BT>
__global__ void lstm_scan(const float* __restrict__ whh)
{
    constexpr int G  = 4 * H;
    constexpr int KP = (H + 3) & ~3;
    extern __shared__ float sm[];
    float* w_s = sm;                 // G * KP
    float* h_s = sm + G * KP;        // BT * KP
    float* g_s = h_s + BT * KP;      // BT * G

    const int j  = threadIdx.x;
    const int b0 = blockIdx.x * BT;

    for (int idx = j; idx < G * KP; idx += G) {
        int n = idx / KP, k = idx - n * KP;
        w_s[idx] = (k < H) ? whh[n * H + k] : 0.0f;
    }
    for (int idx = j; idx < BT * KP; idx += G) h_s[idx] = 0.0f;

    float c[BT];
    #pragma unroll
    for (int b = 0; b < BT; ++b) c[b] = 0.0f;

    __syncthreads();

    float nxt[BT];
    {
        const float* xp = g_xg + (size_t)b0 * G + j;
        #pragma unroll
        for (int b = 0; b < BT; ++b) nxt[b] = xp[b * G];
    }

    for (int t = 0; t < T_STEPS; ++t) {
        float acc[BT];
        #pragma unroll
        for (int b = 0; b < BT; ++b) acc[b] = nxt[b];

        if (t + 1 < T_STEPS) {
            const float* xq = g_xg + ((size_t)(t + 1) * B_SIZE + b0) * G + j;
            #pragma unroll
            for (int b = 0; b < BT; ++b) nxt[b] = xq[b * G];
        }

        for (int k = 0; k < KP; k += 4) {
            float4 wv = *(const float4*)&w_s[j * KP + k];
            #pragma unroll
            for (int b = 0; b < BT; ++b) {
                float4 hv = *(const float4*)&h_s[b * KP + k];
                acc[b] = fmaf(wv.x, hv.x, acc[b]);
                acc[b] = fmaf(wv.y, hv.y, acc[b]);
                acc[b] = fmaf(wv.z, hv.z, acc[b]);
                acc[b] = fmaf(wv.w, hv.w, acc[b]);
            }
        }

        #pragma unroll
        for (int b = 0; b < BT; ++b) g_s[b * G + j] = acc[b];
        __syncthreads();

        if (j < H) {
            #pragma unroll
            for (int b = 0; b < BT; ++b) {
                float gi = g_s[b * G + j];
                float gf = g_s[b * G + j + H];
                float gg = g_s[b * G + j + 2 * H];
                float go = g_s[b * G + j + 3 * H];
                float cn = sigf(gf) * c[b] + sigf(gi) * tanhf_(gg);
                c[b] = cn;
                float hv = sigf(go) * tanhf_(cn);
                h_s[b * KP + j] = hv;
                g_h[((size_t)t * B_SIZE + b0 + b) * H + j] = hv;
            }
        }
        __syncthreads();
    }
}

// ---------------------------------------------------------------------------
// Final linear: out[m] = sum_k g_h[m][k] * w[k] + b, K = 25
// ---------------------------------------------------------------------------
__global__ void linear_out(const float* __restrict__ wl,
                           const float* __restrict__ bl,
                           float* __restrict__ out)
{
    __shared__ float sm[256 * H3];
    __shared__ float wsh[H3];
    const int tid = threadIdx.x;
    const size_t base = (size_t)blockIdx.x * 256 * H3;

    for (int idx = tid; idx < 256 * H3; idx += 256) sm[idx] = g_h[base + idx];
    if (tid < H3) wsh[tid] = wl[tid];
    __syncthreads();

    float a = bl[0];
    #pragma unroll
    for (int k = 0; k < H3; ++k) a = fmaf(sm[tid * H3 + k], wsh[k], a);
    out[(size_t)blockIdx.x * 256 + tid] = a;
}

// ---------------------------------------------------------------------------
extern "C" void kernel_launch(void* const* d_in, const int* in_sizes, int n_in,
                              void* d_out, int out_size)
{
    const float* x     = (const float*)d_in[0];
    const float* w_ih1 = (const float*)d_in[1];
    const float* w_hh1 = (const float*)d_in[2];
    const float* b_ih1 = (const float*)d_in[3];
    const float* b_hh1 = (const float*)d_in[4];
    const float* w_ih2 = (const float*)d_in[5];
    const float* w_hh2 = (const float*)d_in[6];
    const float* b_ih2 = (const float*)d_in[7];
    const float* b_hh2 = (const float*)d_in[8];
    const float* w_ih3 = (const float*)d_in[9];
    const float* w_hh3 = (const float*)d_in[10];
    const float* b_ih3 = (const float*)d_in[11];
    const float* b_hh3 = (const float*)d_in[12];
    const float* w_lin = (const float*)d_in[13];
    const float* b_lin = (const float*)d_in[14];
    float* out = (float*)d_out;

    const int SZ_G1 = (400 * 64 + 128 * 64) * 4;            // 135168
    const int SZ_G2 = (200 * 100 + 128 * 100) * 4;          // 131200
    const int SZ_G3 = (100 * 52 + 128 * 52) * 4;            // 31616... computed below
    const int SZ_S1 = (400 * 100 + 4 * 100 + 4 * 400) * 4;  // 168000
    const int SZ_S2 = (200 * 52 + 4 * 52 + 4 * 200) * 4;    // 45632
    const int SZ_S3 = (100 * 28 + 4 * 28 + 4 * 100) * 4;    // 13248

    cudaFuncSetAttribute(xg_gemm<64>,  cudaFuncAttributeMaxDynamicSharedMemorySize, SZ_G1);
    cudaFuncSetAttribute(xg_gemm<100>, cudaFuncAttributeMaxDynamicSharedMemorySize, SZ_G2);
    cudaFuncSetAttribute(xg_gemm<50>,  cudaFuncAttributeMaxDynamicSharedMemorySize, SZ_G3);
    cudaFuncSetAttribute(lstm_scan<100, 4>, cudaFuncAttributeMaxDynamicSharedMemorySize, SZ_S1);
    cudaFuncSetAttribute(lstm_scan<50, 4>,  cudaFuncAttributeMaxDynamicSharedMemorySize, SZ_S2);
    cudaFuncSetAttribute(lstm_scan<25, 4>,  cudaFuncAttributeMaxDynamicSharedMemorySize, SZ_S3);

    const int GRID_M = M_ROWS / 128;  // 2048
    const int GRID_B = B_SIZE / 4;    // 128

    // Layer 1
    xg_gemm<64><<<GRID_M, 256, SZ_G1>>>(x, w_ih1, b_ih1, b_hh1, 4 * H1);
    lstm_scan<100, 4><<<GRID_B, 400, SZ_S1>>>(w_hh1);
    // Layer 2 (nullptr -> read g_h)
    xg_gemm<100><<<GRID_M, 256, SZ_G2>>>(nullptr, w_ih2, b_ih2, b_hh2, 4 * H2);
    lstm_scan<50, 4><<<GRID_B, 200, SZ_S2>>>(w_hh2);
    // Layer 3
    xg_gemm<50><<<GRID_M, 256, SZ_G3>>>(nullptr, w_ih3, b_ih3, b_hh3, 4 * H3);
    lstm_scan<25, 4><<<GRID_B, 100, SZ_S3>>>(w_hh3);
    // Output
    linear_out<<<M_ROWS / 256, 256>>>(w_lin, b_lin, out);
}

// round 4
// speedup vs baseline: 1.3362x; 1.3362x over previous
#include <cuda_runtime.h>
#include <cuda_bf16.h>
#include <cstddef>

#define T_STEPS 512
#define B_SIZE  512
#define NIN     64
#define H1      100
#define H2      50
#define H3      25
#define M_ROWS  (T_STEPS * B_SIZE)   // 262144

// Scratch: static device globals.
__device__ float g_xg[(size_t)M_ROWS * 4 * H1];   // reused per layer
__device__ float g_h [(size_t)M_ROWS * H1];       // reused per layer

__device__ __forceinline__ float sigf(float x) {
    return 1.0f / (1.0f + __expf(-x));
}
__device__ __forceinline__ float tanhf_(float x) {
    return 1.0f - 2.0f / (__expf(2.0f * x) + 1.0f);
}

// ---------------------------------------------------------------------------
// xg GEMM: g_xg[M, N] = inp[M, K] @ w[N, K]^T + bia[N] + bib[N]
// inp == nullptr -> read from g_h (layers 2, 3).
// TM = 128 rows/CTA, 256 threads. W streamed in 64-row tiles (small smem ->
// multiple resident CTAs). Exact remainder path (16-col, V=1) avoids padding
// waste for N = 400 / 200 / 100.
// ---------------------------------------------------------------------------
template <int K, int N>
__global__ void xg_gemm(const float* __restrict__ inp_,
                        const float* __restrict__ w,
                        const float* __restrict__ bia,
                        const float* __restrict__ bib)
{
    const float* inp = (inp_ != nullptr) ? inp_ : (const float*)g_h;

    constexpr int KP    = (K + 3) & ~3;
    constexpr int TM    = 128;
    constexpr int NFULL = (N / 64) * 64;

    extern __shared__ float sm[];
    float* a_s = sm;             // TM * KP
    float* w_s = sm + TM * KP;   // 64 * KP

    const int tid = threadIdx.x;
    const size_t m0 = (size_t)blockIdx.x * TM;

    for (int idx = tid; idx < TM * KP; idx += 256) {
        int r = idx / KP, k = idx - r * KP;
        a_s[idx] = (k < K) ? inp[(m0 + r) * K + k] : 0.0f;
    }

    const int tr = tid >> 4;    // 0..15
    const int tc = tid & 15;    // 0..15
    const int r0 = tr * 8;

    // full 64-column blocks
    for (int nc = 0; nc < NFULL; nc += 64) {
        __syncthreads();   // a_s ready (first iter) / w_s readers done (later)
        for (int idx = tid; idx < 64 * KP; idx += 256) {
            int n = idx / KP, k = idx - n * KP;
            w_s[idx] = (k < K) ? w[(nc + n) * K + k] : 0.0f;
        }
        __syncthreads();

        float acc[8][4];
        #pragma unroll
        for (int u = 0; u < 8; ++u)
            #pragma unroll
            for (int v = 0; v < 4; ++v) acc[u][v] = 0.0f;

        for (int k = 0; k < KP; k += 4) {
            float4 wv[4];
            #pragma unroll
            for (int v = 0; v < 4; ++v)
                wv[v] = *(const float4*)&w_s[(tc + v * 16) * KP + k];
            #pragma unroll
            for (int u = 0; u < 8; ++u) {
                float4 av = *(const float4*)&a_s[(r0 + u) * KP + k];
                #pragma unroll
                for (int v = 0; v < 4; ++v) {
                    acc[u][v] = fmaf(av.x, wv[v].x, acc[u][v]);
                    acc[u][v] = fmaf(av.y, wv[v].y, acc[u][v]);
                    acc[u][v] = fmaf(av.z, wv[v].z, acc[u][v]);
                    acc[u][v] = fmaf(av.w, wv[v].w, acc[u][v]);
                }
            }
        }

        #pragma unroll
        for (int v = 0; v < 4; ++v) {
            int n = nc + tc + v * 16;
            float bb = bia[n] + bib[n];
            #pragma unroll
            for (int u = 0; u < 8; ++u)
                g_xg[(m0 + r0 + u) * N + n] = acc[u][v] + bb;
        }
    }

    // remainder columns, 16 at a time (V = 1)
    for (int nc = NFULL; nc < N; nc += 16) {
        __syncthreads();
        for (int idx = tid; idx < 16 * KP; idx += 256) {
            int n = idx / KP, k = idx - n * KP;
            int col = nc + n; if (col >= N) col = N - 1;
            w_s[idx] = (k < K) ? w[col * K + k] : 0.0f;
        }
        __syncthreads();

        float acc8[8];
        #pragma unroll
        for (int u = 0; u < 8; ++u) acc8[u] = 0.0f;

        for (int k = 0; k < KP; k += 4) {
            float4 wv = *(const float4*)&w_s[tc * KP + k];
            #pragma unroll
            for (int u = 0; u < 8; ++u) {
                float4 av = *(const float4*)&a_s[(r0 + u) * KP + k];
                acc8[u] = fmaf(av.x, wv.x, acc8[u]);
                acc8[u] = fmaf(av.y, wv.y, acc8[u]);
                acc8[u] = fmaf(av.z, wv.z, acc8[u]);
                acc8[u] = fmaf(av.w, wv.w, acc8[u]);
            }
        }

        int col = nc + tc;
        if (col < N) {
            float bb = bia[col] + bib[col];
            #pragma unroll
            for (int u = 0; u < 8; ++u)
                g_xg[(m0 + r0 + u) * N + col] = acc8[u] + bb;
        }
    }
}

// ---------------------------------------------------------------------------
// LSTM scan: per CTA, BT batch elements for all T steps. No inter-CTA sync.
// Matvec: thread j (< 4H) owns gate row j for all BT batches (W row in smem,
// conflict-free; h broadcast). Epilogue: the SAME 4H threads re-map to
// (b, j) pairs -- 4H pairs exactly -- so the pointwise phase is 4x parallel
// and each thread keeps one c value in a register.
// ---------------------------------------------------------------------------
template <int H, int BT>
__global__ void lstm_scan(const float* __restrict__ whh)
{
    constexpr int G  = 4 * H;
    constexpr int KP = (H + 3) & ~3;
    extern __shared__ float sm[];
    float* w_s = sm;                 // G * KP
    float* h_s = sm + G * KP;        // BT * KP
    float* g_s = h_s + BT * KP;      // BT * G

    const int tid  = threadIdx.x;
    const int nthr = blockDim.x;
    const int b0   = blockIdx.x * BT;

    for (int idx = tid; idx < G * KP; idx += nthr) {
        int n = idx / KP, k = idx - n * KP;
        w_s[idx] = (k < H) ? whh[n * H + k] : 0.0f;
    }
    for (int idx = tid; idx < BT * KP; idx += nthr) h_s[idx] = 0.0f;

    const int eb = tid / H;          // epilogue pair (valid when tid < G)
    const int ej = tid - eb * H;
    float c = 0.0f;

    __syncthreads();

    float nxt[BT];
    if (tid < G) {
        const float* xp = g_xg + (size_t)b0 * G + tid;
        #pragma unroll
        for (int b = 0; b < BT; ++b) nxt[b] = xp[b * G];
    }

    for (int t = 0; t < T_STEPS; ++t) {
        if (tid < G) {
            float acc[BT];
            #pragma unroll
            for (int b = 0; b < BT; ++b) acc[b] = nxt[b];

            if (t + 1 < T_STEPS) {
                const float* xq = g_xg + ((size_t)(t + 1) * B_SIZE + b0) * G + tid;
                #pragma unroll
                for (int b = 0; b < BT; ++b) nxt[b] = xq[b * G];
            }

            const float* wr = w_s + tid * KP;
            for (int k = 0; k < KP; k += 4) {
                float4 wv = *(const float4*)(wr + k);
                #pragma unroll
                for (int b = 0; b < BT; ++b) {
                    float4 hv = *(const float4*)&h_s[b * KP + k];
                    acc[b] = fmaf(wv.x, hv.x, acc[b]);
                    acc[b] = fmaf(wv.y, hv.y, acc[b]);
                    acc[b] = fmaf(wv.z, hv.z, acc[b]);
                    acc[b] = fmaf(wv.w, hv.w, acc[b]);
                }
            }
            #pragma unroll
            for (int b = 0; b < BT; ++b) g_s[b * G + tid] = acc[b];
        }
        __syncthreads();

        if (tid < G) {
            const float* gp = g_s + eb * G + ej;
            float gi = gp[0];
            float gf = gp[H];
            float gg = gp[2 * H];
            float go = gp[3 * H];
            float cn = sigf(gf) * c + sigf(gi) * tanhf_(gg);
            c = cn;
            float hv = sigf(go) * tanhf_(cn);
            h_s[eb * KP + ej] = hv;
            g_h[((size_t)t * B_SIZE + b0 + eb) * H + ej] = hv;
        }
        __syncthreads();
    }
}

// ---------------------------------------------------------------------------
// Final linear: out[m] = sum_k g_h[m][k] * w[k] + b, K = 25
// ---------------------------------------------------------------------------
__global__ void linear_out(const float* __restrict__ wl,
                           const float* __restrict__ bl,
                           float* __restrict__ out)
{
    __shared__ float sm[256 * H3];
    __shared__ float wsh[H3];
    const int tid = threadIdx.x;
    const size_t base = (size_t)blockIdx.x * 256 * H3;

    for (int idx = tid; idx < 256 * H3; idx += 256) sm[idx] = g_h[base + idx];
    if (tid < H3) wsh[tid] = wl[tid];
    __syncthreads();

    float a = bl[0];
    #pragma unroll
    for (int k = 0; k < H3; ++k) a = fmaf(sm[tid * H3 + k], wsh[k], a);
    out[(size_t)blockIdx.x * 256 + tid] = a;
}

// ---------------------------------------------------------------------------
extern "C" void kernel_launch(void* const* d_in, const int* in_sizes, int n_in,
                              void* d_out, int out_size)
{
    const float* x     = (const float*)d_in[0];
    const float* w_ih1 = (const float*)d_in[1];
    const float* w_hh1 = (const float*)d_in[2];
    const float* b_ih1 = (const float*)d_in[3];
    const float* b_hh1 = (const float*)d_in[4];
    const float* w_ih2 = (const float*)d_in[5];
    const float* w_hh2 = (const float*)d_in[6];
    const float* b_ih2 = (const float*)d_in[7];
    const float* b_hh2 = (const float*)d_in[8];
    const float* w_ih3 = (const float*)d_in[9];
    const float* w_hh3 = (const float*)d_in[10];
    const float* b_ih3 = (const float*)d_in[11];
    const float* b_hh3 = (const float*)d_in[12];
    const float* w_lin = (const float*)d_in[13];
    const float* b_lin = (const float*)d_in[14];
    float* out = (float*)d_out;

    // smem sizes (floats * 4)
    const int SZ_G1 = (128 + 64) * 64  * 4;                  // 49152
    const int SZ_G2 = (128 + 64) * 100 * 4;                  // 76800
    const int SZ_G3 = (128 + 64) * 52  * 4;                  // 39936
    const int SZ_S1 = (400 * 100 + 4 * 100 + 4 * 400) * 4;   // 168000
    const int SZ_S2 = (200 * 52  + 4 * 52  + 4 * 200) * 4;   // 45632
    const int SZ_S3 = (100 * 28  + 4 * 28  + 4 * 100) * 4;   // 13248

    cudaFuncSetAttribute(xg_gemm<64, 400>,  cudaFuncAttributeMaxDynamicSharedMemorySize, SZ_G1);
    cudaFuncSetAttribute(xg_gemm<100, 200>, cudaFuncAttributeMaxDynamicSharedMemorySize, SZ_G2);
    cudaFuncSetAttribute(xg_gemm<50, 100>,  cudaFuncAttributeMaxDynamicSharedMemorySize, SZ_G3);
    cudaFuncSetAttribute(lstm_scan<100, 4>, cudaFuncAttributeMaxDynamicSharedMemorySize, SZ_S1);
    cudaFuncSetAttribute(lstm_scan<50, 4>,  cudaFuncAttributeMaxDynamicSharedMemorySize, SZ_S2);
    cudaFuncSetAttribute(lstm_scan<25, 4>,  cudaFuncAttributeMaxDynamicSharedMemorySize, SZ_S3);

    const int GRID_M = M_ROWS / 128;  // 2048
    const int GRID_B = B_SIZE / 4;    // 128

    // Layer 1
    xg_gemm<64, 400><<<GRID_M, 256, SZ_G1>>>(x, w_ih1, b_ih1, b_hh1);
    lstm_scan<100, 4><<<GRID_B, 416, SZ_S1>>>(w_hh1);
    // Layer 2 (nullptr -> read g_h)
    xg_gemm<100, 200><<<GRID_M, 256, SZ_G2>>>(nullptr, w_ih2, b_ih2, b_hh2);
    lstm_scan<50, 4><<<GRID_B, 224, SZ_S2>>>(w_hh2);
    // Layer 3
    xg_gemm<50, 100><<<GRID_M, 256, SZ_G3>>>(nullptr, w_ih3, b_ih3, b_hh3);
    lstm_scan<25, 4><<<GRID_B, 128, SZ_S3>>>(w_hh3);
    // Output
    linear_out<<<M_ROWS / 256, 256>>>(w_lin, b_lin, out);
}

// round 5
// speedup vs baseline: 1.6043x; 1.2006x over previous
#include <cuda_runtime.h>
#include <cuda_bf16.h>
#include <cstddef>

#define T_STEPS 512
#define B_SIZE  512
#define NIN     64
#define H1      100
#define H2      50
#define H3      25
#define M_ROWS  (T_STEPS * B_SIZE)   // 262144

// Scratch: static device globals.
__device__ float g_xg[(size_t)M_ROWS * 4 * H1];   // reused per layer
__device__ float g_h [(size_t)M_ROWS * H1];       // reused per layer

__device__ __forceinline__ float sigf(float x) {
    return 1.0f / (1.0f + __expf(-x));
}
__device__ __forceinline__ float tanhf_(float x) {
    return 1.0f - 2.0f / (__expf(2.0f * x) + 1.0f);
}

// ---- packed fp32x2 helpers (sm_100+) --------------------------------------
__device__ __forceinline__ unsigned long long ffma2(unsigned long long a,
                                                    unsigned long long b,
                                                    unsigned long long c) {
    unsigned long long d;
    asm("fma.rn.f32x2 %0, %1, %2, %3;" : "=l"(d) : "l"(a), "l"(b), "l"(c));
    return d;
}
__device__ __forceinline__ float sum2(unsigned long long a) {
    float lo, hi;
    asm("mov.b64 {%0, %1}, %2;" : "=f"(lo), "=f"(hi) : "l"(a));
    return lo + hi;
}
__device__ __forceinline__ unsigned long long pack2(float lo, float hi) {
    unsigned long long d;
    asm("mov.b64 %0, {%1, %2};" : "=l"(d) : "f"(lo), "f"(hi));
    return d;
}
union F4U2 { float4 f; unsigned long long u[2]; };

// ---------------------------------------------------------------------------
// xg GEMM: g_xg[M, N] = inp[M, K] @ w[N, K]^T + bia[N] + bib[N]
// inp == nullptr -> read from g_h (layers 2, 3).
// TM = 128 rows/CTA, 256 threads, W streamed in 64-row tiles.
// Inner product uses packed f32x2 FMA over k-pairs (half the FMA instrs).
// ---------------------------------------------------------------------------
template <int K, int N>
__global__ void __launch_bounds__(256, 2)
xg_gemm(const float* __restrict__ inp_,
        const float* __restrict__ w,
        const float* __restrict__ bia,
        const float* __restrict__ bib)
{
    const float* inp = (inp_ != nullptr) ? inp_ : (const float*)g_h;

    constexpr int KP    = (K + 3) & ~3;
    constexpr int TM    = 128;
    constexpr int NFULL = (N / 64) * 64;

    extern __shared__ float sm[];
    float* a_s = sm;             // TM * KP
    float* w_s = sm + TM * KP;   // 64 * KP

    const int tid = threadIdx.x;
    const size_t m0 = (size_t)blockIdx.x * TM;

    for (int idx = tid; idx < TM * KP; idx += 256) {
        int r = idx / KP, k = idx - r * KP;
        a_s[idx] = (k < K) ? inp[(m0 + r) * K + k] : 0.0f;
    }

    const int tr = tid >> 4;    // 0..15
    const int tc = tid & 15;    // 0..15
    const int r0 = tr * 8;

    // full 64-column blocks
    for (int nc = 0; nc < NFULL; nc += 64) {
        __syncthreads();
        for (int idx = tid; idx < 64 * KP; idx += 256) {
            int n = idx / KP, k = idx - n * KP;
            w_s[idx] = (k < K) ? w[(nc + n) * K + k] : 0.0f;
        }
        __syncthreads();

        unsigned long long acc2[8][4];
        #pragma unroll
        for (int u = 0; u < 8; ++u)
            #pragma unroll
            for (int v = 0; v < 4; ++v) acc2[u][v] = 0ull;

        for (int k = 0; k < KP; k += 4) {
            F4U2 wv[4];
            #pragma unroll
            for (int v = 0; v < 4; ++v)
                wv[v] = *(const F4U2*)&w_s[(tc + v * 16) * KP + k];
            #pragma unroll
            for (int u = 0; u < 8; ++u) {
                F4U2 av = *(const F4U2*)&a_s[(r0 + u) * KP + k];
                #pragma unroll
                for (int v = 0; v < 4; ++v) {
                    acc2[u][v] = ffma2(av.u[0], wv[v].u[0], acc2[u][v]);
                    acc2[u][v] = ffma2(av.u[1], wv[v].u[1], acc2[u][v]);
                }
            }
        }

        #pragma unroll
        for (int v = 0; v < 4; ++v) {
            int n = nc + tc + v * 16;
            float bb = bia[n] + bib[n];
            #pragma unroll
            for (int u = 0; u < 8; ++u)
                g_xg[(m0 + r0 + u) * N + n] = sum2(acc2[u][v]) + bb;
        }
    }

    // remainder columns, 16 at a time
    for (int nc = NFULL; nc < N; nc += 16) {
        __syncthreads();
        for (int idx = tid; idx < 16 * KP; idx += 256) {
            int n = idx / KP, k = idx - n * KP;
            int col = nc + n; if (col >= N) col = N - 1;
            w_s[idx] = (k < K) ? w[col * K + k] : 0.0f;
        }
        __syncthreads();

        unsigned long long acc8[8];
        #pragma unroll
        for (int u = 0; u < 8; ++u) acc8[u] = 0ull;

        for (int k = 0; k < KP; k += 4) {
            F4U2 wv = *(const F4U2*)&w_s[tc * KP + k];
            #pragma unroll
            for (int u = 0; u < 8; ++u) {
                F4U2 av = *(const F4U2*)&a_s[(r0 + u) * KP + k];
                acc8[u] = ffma2(av.u[0], wv.u[0], acc8[u]);
                acc8[u] = ffma2(av.u[1], wv.u[1], acc8[u]);
            }
        }

        int col = nc + tc;
        if (col < N) {
            float bb = bia[col] + bib[col];
            #pragma unroll
            for (int u = 0; u < 8; ++u)
                g_xg[(m0 + r0 + u) * N + col] = sum2(acc8[u]) + bb;
        }
    }
}

// ---------------------------------------------------------------------------
// LSTM scan: per CTA, BT=4 batch elements for all T steps.
// W_hh row lives in REGISTERS (packed k-pairs) -- no W smem traffic at all.
// Matvec: thread j accumulates packed partial sums per batch via f32x2 FMA;
// h reads are warp-broadcast LDS.128. Epilogue: same 4H threads re-map to
// (b, j) pairs, c in a register.
// ---------------------------------------------------------------------------
template <int H, int BLK>
__global__ void __launch_bounds__(BLK, 1)
lstm_scan(const float* __restrict__ whh)
{
    constexpr int G  = 4 * H;
    constexpr int KP = (H + 3) & ~3;
    constexpr int BT = 4;

    __shared__ float h_s[BT * KP];
    __shared__ float g_s[BT * G];

    const int tid = threadIdx.x;
    const int b0  = blockIdx.x * BT;

    // W row -> registers, packed (k, k+1)
    unsigned long long wreg[KP / 2];
    if (tid < G) {
        const float* wr = whh + tid * H;
        #pragma unroll
        for (int k = 0; k < KP; k += 2) {
            float a = (k     < H) ? wr[k]     : 0.0f;
            float b = (k + 1 < H) ? wr[k + 1] : 0.0f;
            wreg[k / 2] = pack2(a, b);
        }
    }
    for (int i = tid; i < BT * KP; i += BLK) h_s[i] = 0.0f;

    const int eb = (tid < G) ? (tid / H) : 0;   // epilogue pair
    const int ej = tid - eb * H;
    float c = 0.0f;

    __syncthreads();

    float nxt[BT];
    if (tid < G) {
        const float* xp = g_xg + (size_t)b0 * G + tid;
        #pragma unroll
        for (int b = 0; b < BT; ++b) nxt[b] = xp[b * G];
    }

    for (int t = 0; t < T_STEPS; ++t) {
        if (tid < G) {
            unsigned long long acc2[BT];
            #pragma unroll
            for (int b = 0; b < BT; ++b) acc2[b] = pack2(nxt[b], 0.0f);

            if (t + 1 < T_STEPS) {
                const float* xq = g_xg + ((size_t)(t + 1) * B_SIZE + b0) * G + tid;
                #pragma unroll
                for (int b = 0; b < BT; ++b) nxt[b] = xq[b * G];
            }

            #pragma unroll
            for (int k = 0; k < KP; k += 4) {
                #pragma unroll
                for (int b = 0; b < BT; ++b) {
                    F4U2 hv = *(const F4U2*)&h_s[b * KP + k];
                    acc2[b] = ffma2(wreg[k / 2],     hv.u[0], acc2[b]);
                    acc2[b] = ffma2(wreg[k / 2 + 1], hv.u[1], acc2[b]);
                }
            }
            #pragma unroll
            for (int b = 0; b < BT; ++b) g_s[b * G + tid] = sum2(acc2[b]);
        }
        __syncthreads();

        if (tid < G) {
            const float* gp = g_s + eb * G + ej;
            float gi = gp[0];
            float gf = gp[H];
            float gg = gp[2 * H];
            float go = gp[3 * H];
            float cn = sigf(gf) * c + sigf(gi) * tanhf_(gg);
            c = cn;
            float hv = sigf(go) * tanhf_(cn);
            h_s[eb * KP + ej] = hv;
            g_h[((size_t)t * B_SIZE + b0 + eb) * H + ej] = hv;
        }
        __syncthreads();
    }
}

// ---------------------------------------------------------------------------
// Final linear: out[m] = sum_k g_h[m][k] * w[k] + b, K = 25
// ---------------------------------------------------------------------------
__global__ void linear_out(const float* __restrict__ wl,
                           const float* __restrict__ bl,
                           float* __restrict__ out)
{
    __shared__ float sm[256 * H3];
    __shared__ float wsh[H3];
    const int tid = threadIdx.x;
    const size_t base = (size_t)blockIdx.x * 256 * H3;

    for (int idx = tid; idx < 256 * H3; idx += 256) sm[idx] = g_h[base + idx];
    if (tid < H3) wsh[tid] = wl[tid];
    __syncthreads();

    float a = bl[0];
    #pragma unroll
    for (int k = 0; k < H3; ++k) a = fmaf(sm[tid * H3 + k], wsh[k], a);
    out[(size_t)blockIdx.x * 256 + tid] = a;
}

// ---------------------------------------------------------------------------
extern "C" void kernel_launch(void* const* d_in, const int* in_sizes, int n_in,
                              void* d_out, int out_size)
{
    const float* x     = (const float*)d_in[0];
    const float* w_ih1 = (const float*)d_in[1];
    const float* w_hh1 = (const float*)d_in[2];
    const float* b_ih1 = (const float*)d_in[3];
    const float* b_hh1 = (const float*)d_in[4];
    const float* w_ih2 = (const float*)d_in[5];
    const float* w_hh2 = (const float*)d_in[6];
    const float* b_ih2 = (const float*)d_in[7];
    const float* b_hh2 = (const float*)d_in[8];
    const float* w_ih3 = (const float*)d_in[9];
    const float* w_hh3 = (const float*)d_in[10];
    const float* b_ih3 = (const float*)d_in[11];
    const float* b_hh3 = (const float*)d_in[12];
    const float* w_lin = (const float*)d_in[13];
    const float* b_lin = (const float*)d_in[14];
    float* out = (float*)d_out;

    // GEMM dynamic smem sizes (floats * 4)
    const int SZ_G1 = (128 + 64) * 64  * 4;   // 49152
    const int SZ_G2 = (128 + 64) * 100 * 4;   // 76800
    const int SZ_G3 = (128 + 64) * 52  * 4;   // 39936

    cudaFuncSetAttribute(xg_gemm<64, 400>,  cudaFuncAttributeMaxDynamicSharedMemorySize, SZ_G1);
    cudaFuncSetAttribute(xg_gemm<100, 200>, cudaFuncAttributeMaxDynamicSharedMemorySize, SZ_G2);
    cudaFuncSetAttribute(xg_gemm<50, 100>,  cudaFuncAttributeMaxDynamicSharedMemorySize, SZ_G3);

    const int GRID_M = M_ROWS / 128;  // 2048
    const int GRID_B = B_SIZE / 4;    // 128

    // Layer 1
    xg_gemm<64, 400><<<GRID_M, 256, SZ_G1>>>(x, w_ih1, b_ih1, b_hh1);
    lstm_scan<100, 416><<<GRID_B, 416>>>(w_hh1);
    // Layer 2 (nullptr -> read g_h)
    xg_gemm<100, 200><<<GRID_M, 256, SZ_G2>>>(nullptr, w_ih2, b_ih2, b_hh2);
    lstm_scan<50, 224><<<GRID_B, 224>>>(w_hh2);
    // Layer 3
    xg_gemm<50, 100><<<GRID_M, 256, SZ_G3>>>(nullptr, w_ih3, b_ih3, b_hh3);
    lstm_scan<25, 128><<<GRID_B, 128>>>(w_hh3);
    // Output
    linear_out<<<M_ROWS / 256, 256>>>(w_lin, b_lin, out);
}